// round 7
// baseline (speedup 1.0000x reference)
#include <cuda_runtime.h>

#define L 16384
#define THREADS 512
#define R 32

// In-register FWHT butterflies over bits [S0, S0+NS) of the register index.
template <int S0, int NS>
__device__ __forceinline__ void fwht_stages(float v[R]) {
#pragma unroll
    for (int s = S0; s < S0 + NS; s++) {
        const int d = 1 << s;
#pragma unroll
        for (int r = 0; r < R; r++) {
            if ((r & d) == 0) {
                float a = v[r];
                float b = v[r + d];
                v[r] = a + b;
                v[r + d] = a - b;
            }
        }
    }
}

extern __shared__ float sh[];

// Swizzle: ph(i) = i ^ ((i>>5)&31). All structured addresses below are the
// hand-folded exact forms of ph() for their pattern (verified bit-by-bit).
// 512 threads, 32 elem each, 2 CTAs/SM (2x64KB smem, 64-reg cap). The R3
// spill came from ptxas front-batching LDG.128s; __syncwarp() fences cap the
// in-flight load temporaries so 64 regs suffice.
__global__ void __launch_bounds__(THREADS, 2) ff_kernel(
    const float* __restrict__ x,
    const float* __restrict__ Bv,
    const float* __restrict__ Gv,
    const int* __restrict__ Pi,
    float* __restrict__ out)
{
    const int t = threadIdx.x;
    const int l = t & 31;       // lane
    const int q = t >> 5;       // warp id, 0..15
    const int row = blockIdx.x;
    const float* xr = x + (size_t)row * L;
    float* outr = out + (size_t)row * L;

    float v[R];
    const int base = t * R;

    // Pass maps:
    //  P1: i = t*32 + r              (bits 0-4 in regs)   exchange to P2: intra-warp
    //  P2: i = q*1024 + r*32 + l     (bits 5-9 in regs)   exchange to P3: CTA-wide
    //  P3: i = r*512 + t             (bits 9-13 in regs; bit9 = r&1 passenger)

    // ---- load x * B (float4, fenced every 2 chunks to stop LDG hoisting) ----
#pragma unroll
    for (int c = 0; c < 8; c++) {
        float4 xv = *reinterpret_cast<const float4*>(xr + base + c * 4);
        float4 bv = *reinterpret_cast<const float4*>(Bv + base + c * 4);
        v[c * 4 + 0] = xv.x * bv.x;
        v[c * 4 + 1] = xv.y * bv.y;
        v[c * 4 + 2] = xv.z * bv.z;
        v[c * 4 + 3] = xv.w * bv.w;
        if ((c & 1) == 1) __syncwarp();
    }

    // ================= FWHT #1 =================
    // P1 (bits 0-4).  ph(base+r) = base + (r^l): exact for base = t*32.
    fwht_stages<0, 5>(v);
#pragma unroll
    for (int r = 0; r < R; r++) sh[base + (r ^ l)] = v[r];
    __syncwarp();                       // P1->P2 exchange is intra-warp

    // P2 (bits 5-9).  ph(q*1024 + r*32 + l) = q*1024 + r*32 + (l^r).
#pragma unroll
    for (int r = 0; r < R; r++) v[r] = sh[q * 1024 + r * 32 + (l ^ r)];
    fwht_stages<0, 5>(v);
#pragma unroll
    for (int r = 0; r < R; r++) sh[q * 1024 + r * 32 + (l ^ r)] = v[r];
    __syncthreads();                    // P2->P3 crosses the CTA

    // P3 (bits 10-13; bit 9 passenger).  ph(r*512 + t) = r*512 + (t ^ (((r&1)<<4)|q)).
#pragma unroll
    for (int r = 0; r < R; r++) v[r] = sh[r * 512 + (t ^ ((((r & 1) << 4)) | q))];
    fwht_stages<1, 4>(v);               // butterflies bits 10-13 (skip passenger bit 9)
#pragma unroll
    for (int r = 0; r < R; r++) sh[r * 512 + (t ^ ((((r & 1) << 4)) | q))] = v[r];
    __syncthreads();

    // ---- permutation gather + gain + combined scale (1/sqrt(N))^2 ----
    // Chunked + fenced: caps ptxas LDG front-batching (the R3 spill source).
    constexpr float SC = 1.0f / 16384.0f;
#pragma unroll
    for (int c = 0; c < 8; c++) {
        int4   p = *reinterpret_cast<const int4*>(Pi + base + c * 4);
        float4 g = *reinterpret_cast<const float4*>(Gv + base + c * 4);
        v[c * 4 + 0] = sh[p.x ^ ((p.x >> 5) & 31)] * (g.x * SC);
        v[c * 4 + 1] = sh[p.y ^ ((p.y >> 5) & 31)] * (g.y * SC);
        v[c * 4 + 2] = sh[p.z ^ ((p.z >> 5) & 31)] * (g.z * SC);
        v[c * 4 + 3] = sh[p.w ^ ((p.w >> 5) & 31)] * (g.w * SC);
        __syncwarp();
    }

    // ================= FWHT #2 =================
    // P1 (gather delivered natural layout: regs = bits 0-4)
    fwht_stages<0, 5>(v);
    __syncthreads();                    // all gathers complete before overwriting sh
#pragma unroll
    for (int r = 0; r < R; r++) sh[base + (r ^ l)] = v[r];
    __syncwarp();

    // P2
#pragma unroll
    for (int r = 0; r < R; r++) v[r] = sh[q * 1024 + r * 32 + (l ^ r)];
    fwht_stages<0, 5>(v);
#pragma unroll
    for (int r = 0; r < R; r++) sh[q * 1024 + r * 32 + (l ^ r)] = v[r];
    __syncthreads();

    // P3 + final store (i = r*512 + t: lane-consecutive -> coalesced STG.32)
#pragma unroll
    for (int r = 0; r < R; r++) v[r] = sh[r * 512 + (t ^ ((((r & 1) << 4)) | q))];
    fwht_stages<1, 4>(v);
#pragma unroll
    for (int r = 0; r < R; r++) outr[r * 512 + t] = v[r];
}

extern "C" void kernel_launch(void* const* d_in, const int* in_sizes, int n_in,
                              void* d_out, int out_size)
{
    const float* x  = (const float*)d_in[0];
    const float* B  = (const float*)d_in[1];
    const float* G  = (const float*)d_in[2];
    const int*   Pi = (const int*)d_in[3];
    float* out = (float*)d_out;

    const int rows = in_sizes[0] / L;   // 4096

    cudaFuncSetAttribute(ff_kernel, cudaFuncAttributeMaxDynamicSharedMemorySize, L * (int)sizeof(float));

    ff_kernel<<<rows, THREADS, L * sizeof(float)>>>(x, B, G, Pi, out);
}

// round 8
// speedup vs baseline: 1.2312x; 1.2312x over previous
#include <cuda_runtime.h>
#include <cstdint>

#define L 16384
#define THREADS 1024
#define R 16

// Swizzle for the R=16 geometry (bijection on [0,16384)).
__device__ __forceinline__ int ph(int i) { return i ^ ((i >> 4) & 31); }

// Named barrier over an aligned 256-thread (8-warp) group.
__device__ __forceinline__ void bar256(int gid) {
    asm volatile("bar.sync %0, %1;" :: "r"(gid + 1), "r"(256) : "memory");
}

// Packed butterfly: (a, b) <- (a+b, a-b), elementwise on float2, one issue
// slot per op via sm_100+ f32x2 ALUs. Bit-identical to scalar fp32.
__device__ __forceinline__ void bfly2(float2& a, float2& b) {
    unsigned long long A = *reinterpret_cast<unsigned long long*>(&a);
    unsigned long long B = *reinterpret_cast<unsigned long long*>(&b);
    unsigned long long S, D;
    asm("add.rn.f32x2 %0, %1, %2;" : "=l"(S) : "l"(A), "l"(B));
    asm("sub.rn.f32x2 %0, %1, %2;" : "=l"(D) : "l"(A), "l"(B));
    a = *reinterpret_cast<float2*>(&S);
    b = *reinterpret_cast<float2*>(&D);
}

// Scalar d=1 stage: butterfly inside each float2.
__device__ __forceinline__ void bf_d1(float2 w[8]) {
#pragma unroll
    for (int j = 0; j < 8; j++) {
        float a = w[j].x, b = w[j].y;
        w[j].x = a + b;
        w[j].y = a - b;
    }
}

// Packed stage: butterfly between float2's at j-distance D2 (= element d of 2*D2).
template <int D2>
__device__ __forceinline__ void bf_pk(float2 w[8]) {
#pragma unroll
    for (int j = 0; j < 8; j++)
        if ((j & D2) == 0) bfly2(w[j], w[j + D2]);
}

// Full 4-bit in-register FWHT (element bits 0..3 of r): d=1,2,4,8.
__device__ __forceinline__ void fwht4(float2 w[8]) {
    bf_d1(w);
    bf_pk<1>(w);
    bf_pk<2>(w);
    bf_pk<4>(w);
}

extern __shared__ float sh[];

__global__ void __launch_bounds__(THREADS, 1) ff_kernel(
    const float* __restrict__ x,
    const float* __restrict__ Bv,
    const float* __restrict__ Gv,
    const int* __restrict__ Pi,
    float* __restrict__ out)
{
    const int t = threadIdx.x;
    const int row = blockIdx.x;
    const float* xr = x + (size_t)row * L;
    float* outr = out + (size_t)row * L;

    // Pass element maps (4 element-index bits in regs per pass):
    //  P1: i = t*16 + r                      (bits 0-3)   exch -> P2: intra-warp
    //  P2: i = q*256 + r*16 + s, t=q*16+s    (bits 4-7)   exch -> P3: 256-thr group
    //  P3: i = u*4096 + r*256 + m, t=u*256+m (bits 8-11)  exch -> P4: CTA
    //  P4: i = (r&3)*4096 + (r>>2)*1024 + t  (bit12=r&1 in-float2, bit13=r&2 packed)
    const int q = t >> 4, s = t & 15;
    const int u = t >> 8, m = t & 255;

    float2 w[8];
    float* vf = reinterpret_cast<float*>(w);   // vf[r] = element r (unrolled const idx)
    const int base = t * R;

    // ---- load x * B (4x float4, coalesced) ----
#pragma unroll
    for (int c = 0; c < 4; c++) {
        float4 xv = *reinterpret_cast<const float4*>(xr + base + c * 4);
        float4 bv = *reinterpret_cast<const float4*>(Bv + base + c * 4);
        vf[c * 4 + 0] = xv.x * bv.x;
        vf[c * 4 + 1] = xv.y * bv.y;
        vf[c * 4 + 2] = xv.z * bv.z;
        vf[c * 4 + 3] = xv.w * bv.w;
    }

    // ================= FWHT #1 =================
    // P1 (bits 0-3)
    fwht4(w);
#pragma unroll
    for (int r = 0; r < R; r++) sh[ph(base + r)] = vf[r];
    __syncwarp();                       // P1->P2 exchange is intra-warp

    // P2 (bits 4-7)
#pragma unroll
    for (int r = 0; r < R; r++) vf[r] = sh[ph(q * 256 + r * 16 + s)];
    fwht4(w);
#pragma unroll
    for (int r = 0; r < R; r++) sh[ph(q * 256 + r * 16 + s)] = vf[r];
    bar256(u);                          // P2->P3 exchange within 256-thread group

    // P3 (bits 8-11)
#pragma unroll
    for (int r = 0; r < R; r++) vf[r] = sh[ph(u * 4096 + r * 256 + m)];
    fwht4(w);
#pragma unroll
    for (int r = 0; r < R; r++) sh[ph(u * 4096 + r * 256 + m)] = vf[r];
    __syncthreads();                    // P3->P4 crosses the CTA

    // P4 (bits 12-13): bit12 = d1 (inside float2), bit13 = packed j-dist 1
    // (bf_pk<1> pairs (0,1),(2,3),... so passenger groups r>>2 are preserved)
#pragma unroll
    for (int r = 0; r < R; r++)
        vf[r] = sh[ph((r & 3) * 4096 + (r >> 2) * 1024 + t)];
    bf_d1(w);
    bf_pk<1>(w);
#pragma unroll
    for (int r = 0; r < R; r++)
        sh[ph((r & 3) * 4096 + (r >> 2) * 1024 + t)] = vf[r];
    __syncthreads();                    // gather reads arbitrary positions

    // ---- permutation gather + gain + combined scale (1/sqrt(N))^2 ----
    constexpr float SC = 1.0f / 16384.0f;
#pragma unroll
    for (int c = 0; c < 4; c++) {
        int4   p = *reinterpret_cast<const int4*>(Pi + base + c * 4);
        float4 g = *reinterpret_cast<const float4*>(Gv + base + c * 4);
        vf[c * 4 + 0] = sh[ph(p.x)] * (g.x * SC);
        vf[c * 4 + 1] = sh[ph(p.y)] * (g.y * SC);
        vf[c * 4 + 2] = sh[ph(p.z)] * (g.z * SC);
        vf[c * 4 + 3] = sh[ph(p.w)] * (g.w * SC);
    }

    // ================= FWHT #2 =================
    // P1 (gather delivered natural layout: regs = bits 0-3)
    fwht4(w);
    __syncthreads();                    // all gathers complete before overwriting sh
#pragma unroll
    for (int r = 0; r < R; r++) sh[ph(base + r)] = vf[r];
    __syncwarp();

    // P2
#pragma unroll
    for (int r = 0; r < R; r++) vf[r] = sh[ph(q * 256 + r * 16 + s)];
    fwht4(w);
#pragma unroll
    for (int r = 0; r < R; r++) sh[ph(q * 256 + r * 16 + s)] = vf[r];
    bar256(u);

    // P3
#pragma unroll
    for (int r = 0; r < R; r++) vf[r] = sh[ph(u * 4096 + r * 256 + m)];
    fwht4(w);
#pragma unroll
    for (int r = 0; r < R; r++) sh[ph(u * 4096 + r * 256 + m)] = vf[r];
    __syncthreads();

    // P4 + final store (coalesced STG.32)
#pragma unroll
    for (int r = 0; r < R; r++)
        vf[r] = sh[ph((r & 3) * 4096 + (r >> 2) * 1024 + t)];
    bf_d1(w);
    bf_pk<1>(w);
#pragma unroll
    for (int r = 0; r < R; r++)
        outr[(r & 3) * 4096 + (r >> 2) * 1024 + t] = vf[r];
}

extern "C" void kernel_launch(void* const* d_in, const int* in_sizes, int n_in,
                              void* d_out, int out_size)
{
    const float* x  = (const float*)d_in[0];
    const float* B  = (const float*)d_in[1];
    const float* G  = (const float*)d_in[2];
    const int*   Pi = (const int*)d_in[3];
    float* out = (float*)d_out;

    const int rows = in_sizes[0] / L;   // 4096

    cudaFuncSetAttribute(ff_kernel, cudaFuncAttributeMaxDynamicSharedMemorySize, L * (int)sizeof(float));

    ff_kernel<<<rows, THREADS, L * sizeof(float)>>>(x, B, G, Pi, out);
}

// round 9
// speedup vs baseline: 1.2670x; 1.0291x over previous
#include <cuda_runtime.h>
#include <cstdint>

#define L 16384
#define THREADS 1024
#define R 16

// Swizzle for the R=16 geometry (bijection on [0,16384)).
__device__ __forceinline__ int ph(int i) { return i ^ ((i >> 4) & 31); }

// Named barrier over an aligned 256-thread (8-warp) group.
__device__ __forceinline__ void bar256(int gid) {
    asm volatile("bar.sync %0, %1;" :: "r"(gid + 1), "r"(256) : "memory");
}

// Packed butterfly: (a, b) <- (a+b, a-b) elementwise on float2 (sm_100+ f32x2).
__device__ __forceinline__ void bfly2(float2& a, float2& b) {
    unsigned long long A = *reinterpret_cast<unsigned long long*>(&a);
    unsigned long long B = *reinterpret_cast<unsigned long long*>(&b);
    unsigned long long S, D;
    asm("add.rn.f32x2 %0, %1, %2;" : "=l"(S) : "l"(A), "l"(B));
    asm("sub.rn.f32x2 %0, %1, %2;" : "=l"(D) : "l"(A), "l"(B));
    a = *reinterpret_cast<float2*>(&S);
    b = *reinterpret_cast<float2*>(&D);
}

__device__ __forceinline__ void bf_d1(float2 w[8]) {
#pragma unroll
    for (int j = 0; j < 8; j++) {
        float a = w[j].x, b = w[j].y;
        w[j].x = a + b;
        w[j].y = a - b;
    }
}

template <int D2>
__device__ __forceinline__ void bf_pk(float2 w[8]) {
#pragma unroll
    for (int j = 0; j < 8; j++)
        if ((j & D2) == 0) bfly2(w[j], w[j + D2]);
}

// Full 4-bit in-register FWHT (element bits 0..3): d=1,2,4,8.
__device__ __forceinline__ void fwht4(float2 w[8]) {
    bf_d1(w);
    bf_pk<1>(w);
    bf_pk<2>(w);
    bf_pk<4>(w);
}

extern __shared__ float sh[];

// Two rows per CTA: every pass region carries 2x independent LDS chains and
// one barrier serves both rows -> halves per-row barrier count, fills the
// ~22% LSU idle seen at R8 (l1tex 77.7% busy, issue 31.8%).
__global__ void __launch_bounds__(THREADS, 1) ff_kernel(
    const float* __restrict__ x,
    const float* __restrict__ Bv,
    const float* __restrict__ Gv,
    const int* __restrict__ Pi,
    float* __restrict__ out)
{
    const int t = threadIdx.x;
    // Pass element maps (identical to the proven single-row kernel):
    //  P1: i = t*16 + r                      (bits 0-3)   exch -> P2: intra-warp
    //  P2: i = q*256 + r*16 + s, t=q*16+s    (bits 4-7)   exch -> P3: 256-thr group
    //  P3: i = u*4096 + r*256 + m, t=u*256+m (bits 8-11)  exch -> P4: CTA
    //  P4: i = (r&3)*4096 + (r>>2)*1024 + t  (bit12 in-float2, bit13 packed)
    const int q = t >> 4, s = t & 15;
    const int u = t >> 8, m = t & 255;

    const int rowA = blockIdx.x * 2;
    const float* xrA = x + (size_t)rowA * L;
    const float* xrB = xrA + L;
    float* outA = out + (size_t)rowA * L;
    float* outB = outA + L;

    float* const shA = sh;
    float* const shB = sh + L;

    float2 wA[8], wB[8];
    float* vA = reinterpret_cast<float*>(wA);
    float* vB = reinterpret_cast<float*>(wB);
    const int base = t * R;

    // ---- load x * B for both rows (coalesced float4) ----
#pragma unroll
    for (int c = 0; c < 4; c++) {
        float4 bv = *reinterpret_cast<const float4*>(Bv + base + c * 4);
        float4 xa = *reinterpret_cast<const float4*>(xrA + base + c * 4);
        float4 xb = *reinterpret_cast<const float4*>(xrB + base + c * 4);
        vA[c * 4 + 0] = xa.x * bv.x;  vB[c * 4 + 0] = xb.x * bv.x;
        vA[c * 4 + 1] = xa.y * bv.y;  vB[c * 4 + 1] = xb.y * bv.y;
        vA[c * 4 + 2] = xa.z * bv.z;  vB[c * 4 + 2] = xb.z * bv.z;
        vA[c * 4 + 3] = xa.w * bv.w;  vB[c * 4 + 3] = xb.w * bv.w;
    }

    // ================= FWHT #1 =================
    // P1 (bits 0-3)
    fwht4(wA);
    fwht4(wB);
#pragma unroll
    for (int r = 0; r < R; r++) shA[ph(base + r)] = vA[r];
#pragma unroll
    for (int r = 0; r < R; r++) shB[ph(base + r)] = vB[r];
    __syncwarp();                       // P1->P2 exchange is intra-warp

    // P2 (bits 4-7)
#pragma unroll
    for (int r = 0; r < R; r++) vA[r] = shA[ph(q * 256 + r * 16 + s)];
#pragma unroll
    for (int r = 0; r < R; r++) vB[r] = shB[ph(q * 256 + r * 16 + s)];
    fwht4(wA);
    fwht4(wB);
#pragma unroll
    for (int r = 0; r < R; r++) shA[ph(q * 256 + r * 16 + s)] = vA[r];
#pragma unroll
    for (int r = 0; r < R; r++) shB[ph(q * 256 + r * 16 + s)] = vB[r];
    bar256(u);                          // P2->P3 exchange within 256-thread group

    // P3 (bits 8-11)
#pragma unroll
    for (int r = 0; r < R; r++) vA[r] = shA[ph(u * 4096 + r * 256 + m)];
#pragma unroll
    for (int r = 0; r < R; r++) vB[r] = shB[ph(u * 4096 + r * 256 + m)];
    fwht4(wA);
    fwht4(wB);
#pragma unroll
    for (int r = 0; r < R; r++) shA[ph(u * 4096 + r * 256 + m)] = vA[r];
#pragma unroll
    for (int r = 0; r < R; r++) shB[ph(u * 4096 + r * 256 + m)] = vB[r];
    __syncthreads();                    // P3->P4 crosses the CTA

    // P4 (bit12 = d1 inside float2, bit13 = packed j-dist 1)
#pragma unroll
    for (int r = 0; r < R; r++) vA[r] = shA[ph((r & 3) * 4096 + (r >> 2) * 1024 + t)];
#pragma unroll
    for (int r = 0; r < R; r++) vB[r] = shB[ph((r & 3) * 4096 + (r >> 2) * 1024 + t)];
    bf_d1(wA); bf_pk<1>(wA);
    bf_d1(wB); bf_pk<1>(wB);
#pragma unroll
    for (int r = 0; r < R; r++) shA[ph((r & 3) * 4096 + (r >> 2) * 1024 + t)] = vA[r];
#pragma unroll
    for (int r = 0; r < R; r++) shB[ph((r & 3) * 4096 + (r >> 2) * 1024 + t)] = vB[r];
    __syncthreads();                    // gather reads arbitrary positions

    // ---- permutation gather + gain + combined scale (1/sqrt(N))^2 ----
    // Pi/G loaded once, used for both rows.
    constexpr float SC = 1.0f / 16384.0f;
#pragma unroll
    for (int c = 0; c < 4; c++) {
        int4   p = *reinterpret_cast<const int4*>(Pi + base + c * 4);
        float4 g = *reinterpret_cast<const float4*>(Gv + base + c * 4);
        float gx = g.x * SC, gy = g.y * SC, gz = g.z * SC, gw = g.w * SC;
        int ax = ph(p.x), ay = ph(p.y), az = ph(p.z), aw = ph(p.w);
        vA[c * 4 + 0] = shA[ax] * gx;  vB[c * 4 + 0] = shB[ax] * gx;
        vA[c * 4 + 1] = shA[ay] * gy;  vB[c * 4 + 1] = shB[ay] * gy;
        vA[c * 4 + 2] = shA[az] * gz;  vB[c * 4 + 2] = shB[az] * gz;
        vA[c * 4 + 3] = shA[aw] * gw;  vB[c * 4 + 3] = shB[aw] * gw;
    }

    // ================= FWHT #2 =================
    // P1 (gather delivered natural layout: regs = bits 0-3)
    fwht4(wA);
    fwht4(wB);
    __syncthreads();                    // all gathers complete before overwriting sh
#pragma unroll
    for (int r = 0; r < R; r++) shA[ph(base + r)] = vA[r];
#pragma unroll
    for (int r = 0; r < R; r++) shB[ph(base + r)] = vB[r];
    __syncwarp();

    // P2
#pragma unroll
    for (int r = 0; r < R; r++) vA[r] = shA[ph(q * 256 + r * 16 + s)];
#pragma unroll
    for (int r = 0; r < R; r++) vB[r] = shB[ph(q * 256 + r * 16 + s)];
    fwht4(wA);
    fwht4(wB);
#pragma unroll
    for (int r = 0; r < R; r++) shA[ph(q * 256 + r * 16 + s)] = vA[r];
#pragma unroll
    for (int r = 0; r < R; r++) shB[ph(q * 256 + r * 16 + s)] = vB[r];
    bar256(u);

    // P3
#pragma unroll
    for (int r = 0; r < R; r++) vA[r] = shA[ph(u * 4096 + r * 256 + m)];
#pragma unroll
    for (int r = 0; r < R; r++) vB[r] = shB[ph(u * 4096 + r * 256 + m)];
    fwht4(wA);
    fwht4(wB);
#pragma unroll
    for (int r = 0; r < R; r++) shA[ph(u * 4096 + r * 256 + m)] = vA[r];
#pragma unroll
    for (int r = 0; r < R; r++) shB[ph(u * 4096 + r * 256 + m)] = vB[r];
    __syncthreads();

    // P4 + final stores (coalesced STG.32)
#pragma unroll
    for (int r = 0; r < R; r++) vA[r] = shA[ph((r & 3) * 4096 + (r >> 2) * 1024 + t)];
#pragma unroll
    for (int r = 0; r < R; r++) vB[r] = shB[ph((r & 3) * 4096 + (r >> 2) * 1024 + t)];
    bf_d1(wA); bf_pk<1>(wA);
    bf_d1(wB); bf_pk<1>(wB);
#pragma unroll
    for (int r = 0; r < R; r++) outA[(r & 3) * 4096 + (r >> 2) * 1024 + t] = vA[r];
#pragma unroll
    for (int r = 0; r < R; r++) outB[(r & 3) * 4096 + (r >> 2) * 1024 + t] = vB[r];
}

extern "C" void kernel_launch(void* const* d_in, const int* in_sizes, int n_in,
                              void* d_out, int out_size)
{
    const float* x  = (const float*)d_in[0];
    const float* B  = (const float*)d_in[1];
    const float* G  = (const float*)d_in[2];
    const int*   Pi = (const int*)d_in[3];
    float* out = (float*)d_out;

    const int rows = in_sizes[0] / L;   // 4096
    const int smem = 2 * L * (int)sizeof(float);   // 128 KB: two rows per CTA

    cudaFuncSetAttribute(ff_kernel, cudaFuncAttributeMaxDynamicSharedMemorySize, smem);

    ff_kernel<<<rows / 2, THREADS, smem>>>(x, B, G, Pi, out);
}

// round 10
// speedup vs baseline: 1.3573x; 1.0713x over previous
#include <cuda_runtime.h>
#include <cstdint>

#define L 16384
#define THREADS 1024
#define R 16

// Swizzle for the R=16 geometry (bijection on [0,16384)).
__device__ __forceinline__ int ph(int i) { return i ^ ((i >> 4) & 31); }

// Named barrier over an aligned 256-thread (8-warp) group.
__device__ __forceinline__ void bar256(int gid) {
    asm volatile("bar.sync %0, %1;" :: "r"(gid + 1), "r"(256) : "memory");
}

// Packed butterfly: (a, b) <- (a+b, a-b) elementwise on float2 (sm_100+ f32x2).
__device__ __forceinline__ void bfly2(float2& a, float2& b) {
    unsigned long long A = *reinterpret_cast<unsigned long long*>(&a);
    unsigned long long B = *reinterpret_cast<unsigned long long*>(&b);
    unsigned long long S, D;
    asm("add.rn.f32x2 %0, %1, %2;" : "=l"(S) : "l"(A), "l"(B));
    asm("sub.rn.f32x2 %0, %1, %2;" : "=l"(D) : "l"(A), "l"(B));
    a = *reinterpret_cast<float2*>(&S);
    b = *reinterpret_cast<float2*>(&D);
}

__device__ __forceinline__ void bf_d1(float2 w[8]) {
#pragma unroll
    for (int j = 0; j < 8; j++) {
        float a = w[j].x, b = w[j].y;
        w[j].x = a + b;
        w[j].y = a - b;
    }
}

template <int D2>
__device__ __forceinline__ void bf_pk(float2 w[8]) {
#pragma unroll
    for (int j = 0; j < 8; j++)
        if ((j & D2) == 0) bfly2(w[j], w[j + D2]);
}

// Full 4-bit in-register FWHT (element bits 0..3): d=1,2,4,8.
__device__ __forceinline__ void fwht4(float2 w[8]) {
    bf_d1(w);
    bf_pk<1>(w);
    bf_pk<2>(w);
    bf_pk<4>(w);
}

extern __shared__ float sh[];

// Two rows per CTA, SEQUENTIAL within each pass region (A then B) so only one
// row's 16 floats are live at a time (the R9 concurrent version held 32 and
// spilled +160MB to DRAM). Barriers still amortize across both rows.
__global__ void __launch_bounds__(THREADS, 1) ff_kernel(
    const float* __restrict__ x,
    const float* __restrict__ Bv,
    const float* __restrict__ Gv,
    const int* __restrict__ Pi,
    float* __restrict__ out)
{
    const int t = threadIdx.x;
    // Pass element maps (identical to the proven kernels):
    //  P1: i = t*16 + r                      (bits 0-3)   exch -> P2: intra-warp
    //  P2: i = q*256 + r*16 + s, t=q*16+s    (bits 4-7)   exch -> P3: 256-thr group
    //  P3: i = u*4096 + r*256 + m, t=u*256+m (bits 8-11)  exch -> P4: CTA
    //  P4: i = (r&3)*4096 + (r>>2)*1024 + t  (bit12 in-float2, bit13 packed)
    const int q = t >> 4, s = t & 15;
    const int u = t >> 8, m = t & 255;

    const int rowA = blockIdx.x * 2;
    const float* xrA = x + (size_t)rowA * L;
    const float* xrB = xrA + L;
    float* outA = out + (size_t)rowA * L;
    float* outB = outA + L;

    float* const shA = sh;
    float* const shB = sh + L;

    float2 w[8];
    float* vf = reinterpret_cast<float*>(w);
    const int base = t * R;

    constexpr float SC = 1.0f / 16384.0f;

    // ---------- P1 + FWHT#1 bits 0-3 ----------
#pragma unroll
    for (int c = 0; c < 4; c++) {
        float4 xa = *reinterpret_cast<const float4*>(xrA + base + c * 4);
        float4 bv = *reinterpret_cast<const float4*>(Bv + base + c * 4);
        vf[c * 4 + 0] = xa.x * bv.x; vf[c * 4 + 1] = xa.y * bv.y;
        vf[c * 4 + 2] = xa.z * bv.z; vf[c * 4 + 3] = xa.w * bv.w;
    }
    fwht4(w);
#pragma unroll
    for (int r = 0; r < R; r++) shA[ph(base + r)] = vf[r];
    __syncwarp();
#pragma unroll
    for (int c = 0; c < 4; c++) {
        float4 xb = *reinterpret_cast<const float4*>(xrB + base + c * 4);
        float4 bv = *reinterpret_cast<const float4*>(Bv + base + c * 4);
        vf[c * 4 + 0] = xb.x * bv.x; vf[c * 4 + 1] = xb.y * bv.y;
        vf[c * 4 + 2] = xb.z * bv.z; vf[c * 4 + 3] = xb.w * bv.w;
    }
    fwht4(w);
#pragma unroll
    for (int r = 0; r < R; r++) shB[ph(base + r)] = vf[r];
    __syncwarp();                       // P1->P2 exchange is intra-warp (both rows)

    // ---------- P2 (bits 4-7) ----------
#pragma unroll
    for (int r = 0; r < R; r++) vf[r] = shA[ph(q * 256 + r * 16 + s)];
    fwht4(w);
#pragma unroll
    for (int r = 0; r < R; r++) shA[ph(q * 256 + r * 16 + s)] = vf[r];
#pragma unroll
    for (int r = 0; r < R; r++) vf[r] = shB[ph(q * 256 + r * 16 + s)];
    fwht4(w);
#pragma unroll
    for (int r = 0; r < R; r++) shB[ph(q * 256 + r * 16 + s)] = vf[r];
    bar256(u);                          // one barrier serves both rows

    // ---------- P3 (bits 8-11) ----------
#pragma unroll
    for (int r = 0; r < R; r++) vf[r] = shA[ph(u * 4096 + r * 256 + m)];
    fwht4(w);
#pragma unroll
    for (int r = 0; r < R; r++) shA[ph(u * 4096 + r * 256 + m)] = vf[r];
#pragma unroll
    for (int r = 0; r < R; r++) vf[r] = shB[ph(u * 4096 + r * 256 + m)];
    fwht4(w);
#pragma unroll
    for (int r = 0; r < R; r++) shB[ph(u * 4096 + r * 256 + m)] = vf[r];
    __syncthreads();

    // ---------- P4 (bits 12-13) ----------
#pragma unroll
    for (int r = 0; r < R; r++) vf[r] = shA[ph((r & 3) * 4096 + (r >> 2) * 1024 + t)];
    bf_d1(w); bf_pk<1>(w);
#pragma unroll
    for (int r = 0; r < R; r++) shA[ph((r & 3) * 4096 + (r >> 2) * 1024 + t)] = vf[r];
#pragma unroll
    for (int r = 0; r < R; r++) vf[r] = shB[ph((r & 3) * 4096 + (r >> 2) * 1024 + t)];
    bf_d1(w); bf_pk<1>(w);
#pragma unroll
    for (int r = 0; r < R; r++) shB[ph((r & 3) * 4096 + (r >> 2) * 1024 + t)] = vf[r];
    __syncthreads();

    // ---------- permutation gather + gain + FWHT#2-P1, row A ----------
#pragma unroll
    for (int c = 0; c < 4; c++) {
        int4   p = *reinterpret_cast<const int4*>(Pi + base + c * 4);
        float4 g = *reinterpret_cast<const float4*>(Gv + base + c * 4);
        vf[c * 4 + 0] = shA[ph(p.x)] * (g.x * SC);
        vf[c * 4 + 1] = shA[ph(p.y)] * (g.y * SC);
        vf[c * 4 + 2] = shA[ph(p.z)] * (g.z * SC);
        vf[c * 4 + 3] = shA[ph(p.w)] * (g.w * SC);
    }
    fwht4(w);
    __syncthreads();                    // all row-A gathers complete
#pragma unroll
    for (int r = 0; r < R; r++) shA[ph(base + r)] = vf[r];

    // ---------- gather + FWHT#2-P1, row B (Pi/G reloaded: L2-resident) ----------
#pragma unroll
    for (int c = 0; c < 4; c++) {
        int4   p = *reinterpret_cast<const int4*>(Pi + base + c * 4);
        float4 g = *reinterpret_cast<const float4*>(Gv + base + c * 4);
        vf[c * 4 + 0] = shB[ph(p.x)] * (g.x * SC);
        vf[c * 4 + 1] = shB[ph(p.y)] * (g.y * SC);
        vf[c * 4 + 2] = shB[ph(p.z)] * (g.z * SC);
        vf[c * 4 + 3] = shB[ph(p.w)] * (g.w * SC);
    }
    fwht4(w);
    __syncthreads();                    // all row-B gathers complete
#pragma unroll
    for (int r = 0; r < R; r++) shB[ph(base + r)] = vf[r];
    __syncwarp();                       // intra-warp exchange into P2 (row A covered by sync above)

    // ---------- FWHT#2 P2 ----------
#pragma unroll
    for (int r = 0; r < R; r++) vf[r] = shA[ph(q * 256 + r * 16 + s)];
    fwht4(w);
#pragma unroll
    for (int r = 0; r < R; r++) shA[ph(q * 256 + r * 16 + s)] = vf[r];
#pragma unroll
    for (int r = 0; r < R; r++) vf[r] = shB[ph(q * 256 + r * 16 + s)];
    fwht4(w);
#pragma unroll
    for (int r = 0; r < R; r++) shB[ph(q * 256 + r * 16 + s)] = vf[r];
    bar256(u);

    // ---------- FWHT#2 P3 ----------
#pragma unroll
    for (int r = 0; r < R; r++) vf[r] = shA[ph(u * 4096 + r * 256 + m)];
    fwht4(w);
#pragma unroll
    for (int r = 0; r < R; r++) shA[ph(u * 4096 + r * 256 + m)] = vf[r];
#pragma unroll
    for (int r = 0; r < R; r++) vf[r] = shB[ph(u * 4096 + r * 256 + m)];
    fwht4(w);
#pragma unroll
    for (int r = 0; r < R; r++) shB[ph(u * 4096 + r * 256 + m)] = vf[r];
    __syncthreads();

    // ---------- FWHT#2 P4 + final stores (coalesced STG.32) ----------
#pragma unroll
    for (int r = 0; r < R; r++) vf[r] = shA[ph((r & 3) * 4096 + (r >> 2) * 1024 + t)];
    bf_d1(w); bf_pk<1>(w);
#pragma unroll
    for (int r = 0; r < R; r++) outA[(r & 3) * 4096 + (r >> 2) * 1024 + t] = vf[r];
#pragma unroll
    for (int r = 0; r < R; r++) vf[r] = shB[ph((r & 3) * 4096 + (r >> 2) * 1024 + t)];
    bf_d1(w); bf_pk<1>(w);
#pragma unroll
    for (int r = 0; r < R; r++) outB[(r & 3) * 4096 + (r >> 2) * 1024 + t] = vf[r];
}

extern "C" void kernel_launch(void* const* d_in, const int* in_sizes, int n_in,
                              void* d_out, int out_size)
{
    const float* x  = (const float*)d_in[0];
    const float* B  = (const float*)d_in[1];
    const float* G  = (const float*)d_in[2];
    const int*   Pi = (const int*)d_in[3];
    float* out = (float*)d_out;

    const int rows = in_sizes[0] / L;   // 4096
    const int smem = 2 * L * (int)sizeof(float);   // 128 KB: two rows per CTA

    cudaFuncSetAttribute(ff_kernel, cudaFuncAttributeMaxDynamicSharedMemorySize, smem);

    ff_kernel<<<rows / 2, THREADS, smem>>>(x, B, G, Pi, out);
}